// round 1
// baseline (speedup 1.0000x reference)
#include <cuda_runtime.h>

// SpatialTransformer: out[b,c,z,y,x] = trilinear_sample(src[b,c], (x+fx, y+fy, z+fz))
// with zero padding. Sample position simplifies to idx+flow exactly (see analysis).

#define Dd 160
#define Hh 192
#define Ww 160
#define Bb 2
#define Cc 2

__global__ __launch_bounds__(256) void st_kernel(
    const float* __restrict__ src,   // [B, C, D, H, W]
    const float* __restrict__ flow,  // [B, 3, D, H, W]
    float* __restrict__ out)         // [B, C, D, H, W]
{
    constexpr long NV = (long)Dd * Hh * Ww;        // voxels per (b, channel)
    constexpr int HW = Hh * Ww;

    // each thread handles 4 consecutive x positions
    long t = (long)blockIdx.x * blockDim.x + threadIdx.x;
    constexpr long NT = (long)Bb * NV / 4;
    if (t >= NT) return;

    long v4 = t * 4;                 // first voxel (within b*NV flattened)
    int b  = (int)(v4 / NV);
    long v = v4 - (long)b * NV;      // voxel index within volume, multiple of 4
    int x0base = (int)(v % Ww);
    int y      = (int)((v / Ww) % Hh);
    int z      = (int)(v / HW);

    const float* fbase = flow + (long)b * 3 * NV + v;
    float4 fx4 = *reinterpret_cast<const float4*>(fbase);
    float4 fy4 = *reinterpret_cast<const float4*>(fbase + NV);
    float4 fz4 = *reinterpret_cast<const float4*>(fbase + 2 * NV);

    const float* s0 = src + (long)b * Cc * NV;     // channel 0
    const float* s1 = s0 + NV;                     // channel 1

    float o0[4], o1[4];

    float fxs[4] = {fx4.x, fx4.y, fx4.z, fx4.w};
    float fys[4] = {fy4.x, fy4.y, fy4.z, fy4.w};
    float fzs[4] = {fz4.x, fz4.y, fz4.z, fz4.w};

#pragma unroll
    for (int i = 0; i < 4; ++i) {
        float px = (float)(x0base + i) + fxs[i];
        float py = (float)y + fys[i];
        float pz = (float)z + fzs[i];

        float xf = floorf(px), yf = floorf(py), zf = floorf(pz);
        float ax = px - xf, ay = py - yf, az = pz - zf;
        int ix0 = (int)xf, iy0 = (int)yf, iz0 = (int)zf;
        int ix1 = ix0 + 1, iy1 = iy0 + 1, iz1 = iz0 + 1;

        // per-axis weights, zeroed when index out of bounds (zero padding)
        float wx0 = (ix0 >= 0 && ix0 < Ww) ? (1.0f - ax) : 0.0f;
        float wx1 = (ix1 >= 0 && ix1 < Ww) ? ax          : 0.0f;
        float wy0 = (iy0 >= 0 && iy0 < Hh) ? (1.0f - ay) : 0.0f;
        float wy1 = (iy1 >= 0 && iy1 < Hh) ? ay          : 0.0f;
        float wz0 = (iz0 >= 0 && iz0 < Dd) ? (1.0f - az) : 0.0f;
        float wz1 = (iz1 >= 0 && iz1 < Dd) ? az          : 0.0f;

        // clamped addresses (always in-range loads)
        int cx0 = min(max(ix0, 0), Ww - 1);
        int cx1 = min(max(ix1, 0), Ww - 1);
        int cy0 = min(max(iy0, 0), Hh - 1);
        int cy1 = min(max(iy1, 0), Hh - 1);
        int cz0 = min(max(iz0, 0), Dd - 1);
        int cz1 = min(max(iz1, 0), Dd - 1);

        long oz0 = (long)cz0 * HW, oz1 = (long)cz1 * HW;
        long oy0 = (long)cy0 * Ww, oy1 = (long)cy1 * Ww;

        long o000 = oz0 + oy0 + cx0;
        long o001 = oz0 + oy0 + cx1;
        long o010 = oz0 + oy1 + cx0;
        long o011 = oz0 + oy1 + cx1;
        long o100 = oz1 + oy0 + cx0;
        long o101 = oz1 + oy0 + cx1;
        long o110 = oz1 + oy1 + cx0;
        long o111 = oz1 + oy1 + cx1;

        float w000 = wz0 * wy0 * wx0;
        float w001 = wz0 * wy0 * wx1;
        float w010 = wz0 * wy1 * wx0;
        float w011 = wz0 * wy1 * wx1;
        float w100 = wz1 * wy0 * wx0;
        float w101 = wz1 * wy0 * wx1;
        float w110 = wz1 * wy1 * wx0;
        float w111 = wz1 * wy1 * wx1;

        float a0 = 0.f, a1 = 0.f;
        a0 += w000 * __ldg(s0 + o000);  a1 += w000 * __ldg(s1 + o000);
        a0 += w001 * __ldg(s0 + o001);  a1 += w001 * __ldg(s1 + o001);
        a0 += w010 * __ldg(s0 + o010);  a1 += w010 * __ldg(s1 + o010);
        a0 += w011 * __ldg(s0 + o011);  a1 += w011 * __ldg(s1 + o011);
        a0 += w100 * __ldg(s0 + o100);  a1 += w100 * __ldg(s1 + o100);
        a0 += w101 * __ldg(s0 + o101);  a1 += w101 * __ldg(s1 + o101);
        a0 += w110 * __ldg(s0 + o110);  a1 += w110 * __ldg(s1 + o110);
        a0 += w111 * __ldg(s0 + o111);  a1 += w111 * __ldg(s1 + o111);

        o0[i] = a0;
        o1[i] = a1;
    }

    float* obase = out + (long)b * Cc * NV + v;
    *reinterpret_cast<float4*>(obase)      = make_float4(o0[0], o0[1], o0[2], o0[3]);
    *reinterpret_cast<float4*>(obase + NV) = make_float4(o1[0], o1[1], o1[2], o1[3]);
}

extern "C" void kernel_launch(void* const* d_in, const int* in_sizes, int n_in,
                              void* d_out, int out_size) {
    const float* src  = (const float*)d_in[0];
    const float* flow = (const float*)d_in[1];
    float* out = (float*)d_out;

    constexpr long NV = (long)Dd * Hh * Ww;
    constexpr long NT = (long)Bb * NV / 4;   // threads, 4 voxels each
    int threads = 256;
    long blocks = (NT + threads - 1) / threads;
    st_kernel<<<(unsigned)blocks, threads>>>(src, flow, out);
}

// round 2
// speedup vs baseline: 1.2734x; 1.2734x over previous
#include <cuda_runtime.h>

// SpatialTransformer: out[b,c,z,y,x] = trilinear_sample(src[b,c], (x+fx, y+fy, z+fz))
// with zero padding. Normalization in the reference cancels exactly:
// sample position = voxel index + flow.
//
// R2: one voxel per thread, lanes consecutive in x (gather addresses 4B apart
// within a warp -> fewer L1 sectors/wavefronts per gather). All-int addressing.

#define Dd 160
#define Hh 192
#define Ww 160
#define Bb 2
#define Cc 2

__global__ __launch_bounds__(256) void st_kernel(
    const float* __restrict__ src,   // [B, C, D, H, W]
    const float* __restrict__ flow,  // [B, 3, D, H, W]
    float* __restrict__ out)         // [B, C, D, H, W]
{
    constexpr int NV = Dd * Hh * Ww;        // 4,915,200 voxels per (b, channel)
    constexpr int HW = Hh * Ww;
    constexpr int NTOT = Bb * NV;

    int t = blockIdx.x * blockDim.x + threadIdx.x;
    if (t >= NTOT) return;

    int b = t / NV;
    int v = t - b * NV;                     // lane-consecutive in x
    int x = v % Ww;
    int y = (v / Ww) % Hh;
    int z = v / HW;

    const float* fbase = flow + b * (3 * NV) + v;
    float fx = __ldg(fbase);
    float fy = __ldg(fbase + NV);
    float fz = __ldg(fbase + 2 * NV);

    float px = (float)x + fx;
    float py = (float)y + fy;
    float pz = (float)z + fz;

    float xf = floorf(px), yf = floorf(py), zf = floorf(pz);
    float ax = px - xf, ay = py - yf, az = pz - zf;
    int ix0 = (int)xf, iy0 = (int)yf, iz0 = (int)zf;
    int ix1 = ix0 + 1, iy1 = iy0 + 1, iz1 = iz0 + 1;

    // per-axis weights, zeroed when the corner index is out of bounds (zero padding)
    float wx0 = (ix0 >= 0 && ix0 < Ww) ? (1.0f - ax) : 0.0f;
    float wx1 = (ix1 >= 0 && ix1 < Ww) ? ax          : 0.0f;
    float wy0 = (iy0 >= 0 && iy0 < Hh) ? (1.0f - ay) : 0.0f;
    float wy1 = (iy1 >= 0 && iy1 < Hh) ? ay          : 0.0f;
    float wz0 = (iz0 >= 0 && iz0 < Dd) ? (1.0f - az) : 0.0f;
    float wz1 = (iz1 >= 0 && iz1 < Dd) ? az          : 0.0f;

    // clamped addresses (loads always in range)
    int cx0 = min(max(ix0, 0), Ww - 1);
    int cx1 = min(max(ix1, 0), Ww - 1);
    int cy0 = min(max(iy0, 0), Hh - 1);
    int cy1 = min(max(iy1, 0), Hh - 1);
    int cz0 = min(max(iz0, 0), Dd - 1);
    int cz1 = min(max(iz1, 0), Dd - 1);

    int oz0 = cz0 * HW, oz1 = cz1 * HW;
    int oy0 = cy0 * Ww, oy1 = cy1 * Ww;

    int o000 = oz0 + oy0 + cx0;
    int o001 = oz0 + oy0 + cx1;
    int o010 = oz0 + oy1 + cx0;
    int o011 = oz0 + oy1 + cx1;
    int o100 = oz1 + oy0 + cx0;
    int o101 = oz1 + oy0 + cx1;
    int o110 = oz1 + oy1 + cx0;
    int o111 = oz1 + oy1 + cx1;

    float wz0y0 = wz0 * wy0;
    float wz0y1 = wz0 * wy1;
    float wz1y0 = wz1 * wy0;
    float wz1y1 = wz1 * wy1;

    float w000 = wz0y0 * wx0;
    float w001 = wz0y0 * wx1;
    float w010 = wz0y1 * wx0;
    float w011 = wz0y1 * wx1;
    float w100 = wz1y0 * wx0;
    float w101 = wz1y0 * wx1;
    float w110 = wz1y1 * wx0;
    float w111 = wz1y1 * wx1;

    const float* s0 = src + b * (Cc * NV);   // channel 0
    const float* s1 = s0 + NV;               // channel 1

    // issue all 16 gathers up front for max MLP
    float v000a = __ldg(s0 + o000), v000b = __ldg(s1 + o000);
    float v001a = __ldg(s0 + o001), v001b = __ldg(s1 + o001);
    float v010a = __ldg(s0 + o010), v010b = __ldg(s1 + o010);
    float v011a = __ldg(s0 + o011), v011b = __ldg(s1 + o011);
    float v100a = __ldg(s0 + o100), v100b = __ldg(s1 + o100);
    float v101a = __ldg(s0 + o101), v101b = __ldg(s1 + o101);
    float v110a = __ldg(s0 + o110), v110b = __ldg(s1 + o110);
    float v111a = __ldg(s0 + o111), v111b = __ldg(s1 + o111);

    float a0 = w000 * v000a;
    float a1 = w000 * v000b;
    a0 = fmaf(w001, v001a, a0);  a1 = fmaf(w001, v001b, a1);
    a0 = fmaf(w010, v010a, a0);  a1 = fmaf(w010, v010b, a1);
    a0 = fmaf(w011, v011a, a0);  a1 = fmaf(w011, v011b, a1);
    a0 = fmaf(w100, v100a, a0);  a1 = fmaf(w100, v100b, a1);
    a0 = fmaf(w101, v101a, a0);  a1 = fmaf(w101, v101b, a1);
    a0 = fmaf(w110, v110a, a0);  a1 = fmaf(w110, v110b, a1);
    a0 = fmaf(w111, v111a, a0);  a1 = fmaf(w111, v111b, a1);

    float* obase = out + b * (Cc * NV) + v;
    obase[0]  = a0;
    obase[NV] = a1;
}

extern "C" void kernel_launch(void* const* d_in, const int* in_sizes, int n_in,
                              void* d_out, int out_size) {
    const float* src  = (const float*)d_in[0];
    const float* flow = (const float*)d_in[1];
    float* out = (float*)d_out;

    constexpr int NTOT = Bb * Dd * Hh * Ww;
    int threads = 256;
    int blocks = (NTOT + threads - 1) / threads;
    st_kernel<<<blocks, threads>>>(src, flow, out);
}